// round 3
// baseline (speedup 1.0000x reference)
#include <cuda_runtime.h>

// Inverse discrete Hough transform, round 3: run-length register reuse.
// out[nc,y,x] = sum_a accT[a,r(a,y,x)][nc]
// Pass A: angles 45..134 (|cos|<=|sin|), 16-px strips along x, writes out.
// Pass B: angles 0..44,135..179, strips along y, writes pBT[nc][x][y].
// Merge: out[nc][y][x] += pBT[nc][x][y] (smem tile transpose-add).

#define NA 180
#define NR 400
#define NC 256
#define OH 256
#define OW 256
#define AR (NA * NR)      // 72000
#define HW (OH * OW)      // 65536

__device__ float  g_accT[AR * NC];    // 73.7 MB: [a*400+r][nc]
__device__ float2 g_trig[NA];
__device__ int    g_offA[90 * HW];    // byte offsets (a*400+r)<<10, [arel][row][col]
__device__ int    g_offB[90 * HW];
__device__ float  g_pBT[NC * HW];     // pass-B partial, [nc][x][y]

__device__ __forceinline__ unsigned long long fadd2(unsigned long long a,
                                                    unsigned long long b) {
    unsigned long long r;
    asm("add.rn.f32x2 %0, %1, %2;" : "=l"(r) : "l"(a), "l"(b));
    return r;
}
__device__ __forceinline__ float u64lo(unsigned long long u) {
    float a, b; asm("mov.b64 {%0,%1}, %2;" : "=f"(a), "=f"(b) : "l"(u)); return a;
}
__device__ __forceinline__ float u64hi(unsigned long long u) {
    float a, b; asm("mov.b64 {%0,%1}, %2;" : "=f"(a), "=f"(b) : "l"(u)); return b;
}

__global__ void k_trig() {
    int a = threadIdx.x;
    if (a < NA) {
        // f32 theta (rn multiply) then correctly-rounded f32 cos/sin via double
        // (immune to fast-math; matches the JAX reference bit-exactly).
        float t = __fmul_rn((float)a, (float)(3.14159265358979323846 / 180.0));
        double td = (double)t;
        g_trig[a] = make_float2((float)cos(td), (float)sin(td));
    }
}

// 32x32 tiled transpose of acc[256][72000] -> g_accT[72000][256]
__global__ void k_transpose(const float* __restrict__ in) {
    __shared__ float tile[32][33];
    int tx = threadIdx.x, ty = threadIdx.y;           // 32 x 8
    int ar = blockIdx.x * 32 + tx;
#pragma unroll
    for (int k = 0; k < 4; k++)
        tile[ty + k * 8][tx] = in[(size_t)(blockIdx.y * 32 + ty + k * 8) * AR + ar];
    __syncthreads();
    int nc2 = blockIdx.y * 32 + tx;
#pragma unroll
    for (int k = 0; k < 4; k++)
        g_accT[(size_t)(blockIdx.x * 32 + ty + k * 8) * NC + nc2] = tile[tx][ty + k * 8];
}

// Precompute exact rho byte-offset tables for both passes.
__global__ void k_tab() {
    int idx = blockIdx.x * 256 + threadIdx.x;         // 180*65536 threads
    int col = idx & 255, row = (idx >> 8) & 255, a = idx >> 16;
    bool isA = (a >= 45 && a < 135);
    int x = isA ? col : row;
    int y = isA ? row : col;
    float2 cs = g_trig[a];
    // exact reference arithmetic: rn(rn(xc*cos) + rn(yc*sin)), round-half-even
    float s = __fadd_rn(__fmul_rn((float)(x - OW / 2), cs.x),
                        __fmul_rn((float)(y - OH / 2), cs.y));
    int off = (a * NR + __float2int_rn(s) + NR / 2) << 10;   // byte offset
    int arel = isA ? (a - 45) : (a < 45 ? a : a - 90);
    int* tab = isA ? g_offA : g_offB;
    tab[(arel << 16) + (row << 8) + col] = off;
}

// Main pass. PASS=0: x-strips -> outp. PASS=1: y-strips -> g_pBT.
// Warp: 16 strip pixels x 128 channels (half), 4 ch/lane.
// 2-angle interleave; run-length predicated loads (uniform predicate).
template <int PASS>
__global__ __launch_bounds__(256, 2) void k_pass(float* __restrict__ outp) {
    int tid = threadIdx.x, w = tid >> 5, l = tid & 31;
    int gsid = blockIdx.x * 8 + w;
    int half = gsid & 1, sid = gsid >> 1;
    int row = sid >> 4, c0 = (sid & 15) << 4;

    const int* tab = (PASS == 0) ? g_offA : g_offB;
    float* dst = (PASS == 0) ? outp : g_pBT;

    unsigned long long base;
    {
        const char* gp = (const char*)g_accT + half * 512 + l * 16;
        asm("cvta.to.global.u64 %0, %1;" : "=l"(base) : "l"(gp));
    }

    unsigned long long a01[16], a23[16];
#pragma unroll
    for (int p = 0; p < 16; p++) { a01[p] = 0ull; a23[p] = 0ull; }

    const int4* tp = (const int4*)(tab + (row << 8) + c0);

    for (int ar = 0; ar < 90; ar += 2) {
        int4 A0 = __ldg(tp),         A1 = __ldg(tp + 1);
        int4 A2 = __ldg(tp + 2),     A3 = __ldg(tp + 3);
        int4 B0 = __ldg(tp + 16384), B1 = __ldg(tp + 16385);
        int4 B2 = __ldg(tp + 16386), B3 = __ldg(tp + 16387);
        tp += 32768;
        int oa[16] = {A0.x, A0.y, A0.z, A0.w, A1.x, A1.y, A1.z, A1.w,
                      A2.x, A2.y, A2.z, A2.w, A3.x, A3.y, A3.z, A3.w};
        int ob[16] = {B0.x, B0.y, B0.z, B0.w, B1.x, B1.y, B1.z, B1.w,
                      B2.x, B2.y, B2.z, B2.w, B3.x, B3.y, B3.z, B3.w};

        unsigned long long va0, va1, vb0, vb1;
        asm("ld.global.nc.v2.u64 {%0,%1}, [%2];"
            : "=l"(va0), "=l"(va1) : "l"(base + (unsigned)oa[0]));
        asm("ld.global.nc.v2.u64 {%0,%1}, [%2];"
            : "=l"(vb0), "=l"(vb1) : "l"(base + (unsigned)ob[0]));
        a01[0] = fadd2(fadd2(a01[0], va0), vb0);
        a23[0] = fadd2(fadd2(a23[0], va1), vb1);
#pragma unroll
        for (int p = 1; p < 16; p++) {
            asm("{\n\t.reg .pred q;\n\tsetp.ne.s32 q, %2, %3;\n\t"
                "@q ld.global.nc.v2.u64 {%0,%1}, [%4];\n\t}"
                : "+l"(va0), "+l"(va1)
                : "r"(oa[p]), "r"(oa[p - 1]), "l"(base + (unsigned)oa[p]));
            asm("{\n\t.reg .pred q;\n\tsetp.ne.s32 q, %2, %3;\n\t"
                "@q ld.global.nc.v2.u64 {%0,%1}, [%4];\n\t}"
                : "+l"(vb0), "+l"(vb1)
                : "r"(ob[p]), "r"(ob[p - 1]), "l"(base + (unsigned)ob[p]));
            a01[p] = fadd2(fadd2(a01[p], va0), vb0);
            a23[p] = fadd2(fadd2(a23[p], va1), vb1);
        }
    }

    // store: channel chb+j, 16 strip pixels contiguous in dst
    int chb = half * 128 + l * 4;
    float* op = dst + (size_t)chb * HW + (row << 8) + c0;
#pragma unroll
    for (int j = 0; j < 4; j++) {
        float t[16];
#pragma unroll
        for (int p = 0; p < 16; p++) {
            unsigned long long u = (j < 2) ? a01[p] : a23[p];
            t[p] = (j & 1) ? u64hi(u) : u64lo(u);
        }
        float4* q = (float4*)(op + (size_t)j * HW);
        q[0] = make_float4(t[0],  t[1],  t[2],  t[3]);
        q[1] = make_float4(t[4],  t[5],  t[6],  t[7]);
        q[2] = make_float4(t[8],  t[9],  t[10], t[11]);
        q[3] = make_float4(t[12], t[13], t[14], t[15]);
    }
}

// out[nc][y][x] += g_pBT[nc][x][y]
__global__ void k_merge(float* __restrict__ out) {
    __shared__ float tile[32][33];
    int tx = threadIdx.x, ty = threadIdx.y;           // 32 x 8
    const float* src = g_pBT + (size_t)blockIdx.z * HW;
    float* o = out + (size_t)blockIdx.z * HW;
    int x0 = blockIdx.x * 32, y0 = blockIdx.y * 32;
#pragma unroll
    for (int k = 0; k < 4; k++)
        tile[ty + k * 8][tx] = src[(size_t)(x0 + ty + k * 8) * OW + y0 + tx];
    __syncthreads();
#pragma unroll
    for (int k = 0; k < 4; k++) {
        size_t oi = (size_t)(y0 + ty + k * 8) * OW + x0 + tx;
        o[oi] += tile[tx][ty + k * 8];
    }
}

extern "C" void kernel_launch(void* const* d_in, const int* in_sizes, int n_in,
                              void* d_out, int out_size) {
    const float* acc = (const float*)d_in[0];
    float* out = (float*)d_out;

    k_trig<<<1, 192>>>();
    k_transpose<<<dim3(AR / 32, NC / 32), dim3(32, 8)>>>(acc);
    k_tab<<<NA * HW / 256, 256>>>();
    k_pass<1><<<1024, 256>>>(out);     // pass B -> g_pBT
    k_pass<0><<<1024, 256>>>(out);     // pass A -> out
    k_merge<<<dim3(8, 8, 256), dim3(32, 8)>>>(out);
}

// round 4
// speedup vs baseline: 1.3392x; 1.3392x over previous
#include <cuda_runtime.h>

// Inverse discrete Hough transform, round 4: run-length register reuse with
// short (8-px) chains, 2-angle interleave, and 3-CTA/SM occupancy.
// out[nc,y,x] = sum_a accT[a*400+r(a,y,x)][nc]
// Pass A: angles 45..134 (|cos| small), 8-px strips along x, writes out.
// Pass B: angles 0..44,135..179, 8-px strips along y, writes pBT[nc][x][y].
// Merge: out[nc][y][x] += pBT[nc][x][y].

#define NA 180
#define NR 400
#define NC 256
#define OH 256
#define OW 256
#define AR (NA * NR)      // 72000
#define HW (OH * OW)      // 65536
#define NSTRIP 8192       // 65536 px / 8 per strip

__device__ float  g_accT[AR * NC];          // 73.7 MB: [a*400+r][nc]
__device__ float2 g_trig[NA];
__device__ int    g_offA[(size_t)NSTRIP * 90 * 8];   // [strip][arel][p] byte offsets
__device__ int    g_offB[(size_t)NSTRIP * 90 * 8];
__device__ float  g_pBT[NC * HW];           // pass-B partial, [nc][x][y]

__device__ __forceinline__ unsigned long long fadd2(unsigned long long a,
                                                    unsigned long long b) {
    unsigned long long r;
    asm("add.rn.f32x2 %0, %1, %2;" : "=l"(r) : "l"(a), "l"(b));
    return r;
}
__device__ __forceinline__ float u64lo(unsigned long long u) {
    float a, b; asm("mov.b64 {%0,%1}, %2;" : "=f"(a), "=f"(b) : "l"(u)); return a;
}
__device__ __forceinline__ float u64hi(unsigned long long u) {
    float a, b; asm("mov.b64 {%0,%1}, %2;" : "=f"(a), "=f"(b) : "l"(u)); return b;
}

__global__ void k_trig() {
    int a = threadIdx.x;
    if (a < NA) {
        // f32 theta (rn multiply), then correctly-rounded f32 cos/sin via
        // double (immune to fast-math; matches the JAX reference bit-exactly).
        float t = __fmul_rn((float)a, (float)(3.14159265358979323846 / 180.0));
        double td = (double)t;
        g_trig[a] = make_float2((float)cos(td), (float)sin(td));
    }
}

// 32x32 tiled transpose of acc[256][72000] -> g_accT[72000][256]
__global__ void k_transpose(const float* __restrict__ in) {
    __shared__ float tile[32][33];
    int tx = threadIdx.x, ty = threadIdx.y;           // 32 x 8
    int ar = blockIdx.x * 32 + tx;
#pragma unroll
    for (int k = 0; k < 4; k++)
        tile[ty + k * 8][tx] = in[(size_t)(blockIdx.y * 32 + ty + k * 8) * AR + ar];
    __syncthreads();
    int nc2 = blockIdx.y * 32 + tx;
#pragma unroll
    for (int k = 0; k < 4; k++)
        g_accT[(size_t)(blockIdx.x * 32 + ty + k * 8) * NC + nc2] = tile[tx][ty + k * 8];
}

// Precompute exact rho byte-offset tables: [strip][arel][p], p = pixel in strip.
__global__ void k_tab() {
    int idx = blockIdx.x * 256 + threadIdx.x;   // 180 * 8192 * 8 threads
    int p = idx & 7;
    int s = (idx >> 3) & (NSTRIP - 1);
    int a = idx >> 16;
    bool isA = (a >= 45 && a < 135);
    int line = s >> 5, q0 = (s & 31) << 3;
    int x = isA ? (q0 + p) : line;
    int y = isA ? line : (q0 + p);
    float2 cs = g_trig[a];
    // exact reference arithmetic: rn(rn(xc*cos) + rn(yc*sin)), round-half-even
    float sum = __fadd_rn(__fmul_rn((float)(x - OW / 2), cs.x),
                          __fmul_rn((float)(y - OH / 2), cs.y));
    int off = (a * NR + __float2int_rn(sum) + NR / 2) << 10;   // byte offset
    int arel = isA ? (a - 45) : (a < 45 ? a : a - 90);
    int* tab = isA ? g_offA : g_offB;
    tab[((size_t)s * 90 + arel) * 8 + p] = off;
}

// Main pass. PASS=0: x-strips -> outp (angles 45..134).
//            PASS=1: y-strips -> g_pBT (angles 0..44,135..179).
// Warp: 8 strip pixels x 128 channels (half of 256), 4 ch/lane (float4).
// Per angle: run-length predicated loads (uniform predicate, chain of 8);
// two angles interleaved = two independent chains.
template <int PASS>
__global__ __launch_bounds__(256, 3) void k_pass(float* __restrict__ outp) {
    int tid = threadIdx.x, w = tid >> 5, l = tid & 31;
    int gw = blockIdx.x * 8 + w;       // global warp id, 0..16383
    int half = gw & 1, s = gw >> 1;    // strip id 0..8191
    int line = s >> 5, p0 = (s & 31) << 3;

    const int* tab = (PASS == 0) ? g_offA : g_offB;
    float* dst = (PASS == 0) ? outp : g_pBT;

    unsigned long long base;
    {
        const char* gp = (const char*)g_accT + half * 512 + l * 16;
        asm("cvta.to.global.u64 %0, %1;" : "=l"(base) : "l"(gp));
    }

    // acc[2p] = channels (c0,c0+1), acc[2p+1] = (c0+2,c0+3) for pixel p
    unsigned long long acc[16];
#pragma unroll
    for (int i = 0; i < 16; i++) acc[i] = 0ull;

    const int4* tp = (const int4*)(tab + (size_t)s * 90 * 8);

    for (int ar = 0; ar < 90; ar += 2) {
        int4 A0 = __ldg(tp),     A1 = __ldg(tp + 1);   // angle ar
        int4 B0 = __ldg(tp + 2), B1 = __ldg(tp + 3);   // angle ar+1
        tp += 4;
        int oa[8] = {A0.x, A0.y, A0.z, A0.w, A1.x, A1.y, A1.z, A1.w};
        int ob[8] = {B0.x, B0.y, B0.z, B0.w, B1.x, B1.y, B1.z, B1.w};

        unsigned long long va0, va1, vb0, vb1;
        asm("ld.global.nc.v2.u64 {%0,%1}, [%2];"
            : "=l"(va0), "=l"(va1) : "l"(base + (unsigned)oa[0]));
        asm("ld.global.nc.v2.u64 {%0,%1}, [%2];"
            : "=l"(vb0), "=l"(vb1) : "l"(base + (unsigned)ob[0]));
        acc[0] = fadd2(fadd2(acc[0], va0), vb0);
        acc[1] = fadd2(fadd2(acc[1], va1), vb1);
#pragma unroll
        for (int p = 1; p < 8; p++) {
            asm("{\n\t.reg .pred q;\n\tsetp.ne.s32 q, %2, %3;\n\t"
                "@q ld.global.nc.v2.u64 {%0,%1}, [%4];\n\t}"
                : "+l"(va0), "+l"(va1)
                : "r"(oa[p]), "r"(oa[p - 1]), "l"(base + (unsigned)oa[p]));
            asm("{\n\t.reg .pred q;\n\tsetp.ne.s32 q, %2, %3;\n\t"
                "@q ld.global.nc.v2.u64 {%0,%1}, [%4];\n\t}"
                : "+l"(vb0), "+l"(vb1)
                : "r"(ob[p]), "r"(ob[p - 1]), "l"(base + (unsigned)ob[p]));
            acc[2 * p]     = fadd2(fadd2(acc[2 * p],     va0), vb0);
            acc[2 * p + 1] = fadd2(fadd2(acc[2 * p + 1], va1), vb1);
        }
    }

    // store: lane channels c0..c0+3, 8 strip pixels contiguous in dst
    int chb = half * 128 + l * 4;
    float* op = dst + (size_t)chb * HW + (line << 8) + p0;
#pragma unroll
    for (int j = 0; j < 4; j++) {
        float t[8];
#pragma unroll
        for (int p = 0; p < 8; p++) {
            unsigned long long u = acc[2 * p + (j >> 1)];
            t[p] = (j & 1) ? u64hi(u) : u64lo(u);
        }
        float4* q = (float4*)(op + (size_t)j * HW);
        q[0] = make_float4(t[0], t[1], t[2], t[3]);
        q[1] = make_float4(t[4], t[5], t[6], t[7]);
    }
}

// out[nc][y][x] += g_pBT[nc][x][y]
__global__ void k_merge(float* __restrict__ out) {
    __shared__ float tile[32][33];
    int tx = threadIdx.x, ty = threadIdx.y;           // 32 x 8
    const float* src = g_pBT + (size_t)blockIdx.z * HW;
    float* o = out + (size_t)blockIdx.z * HW;
    int x0 = blockIdx.x * 32, y0 = blockIdx.y * 32;
#pragma unroll
    for (int k = 0; k < 4; k++)
        tile[ty + k * 8][tx] = src[(size_t)(x0 + ty + k * 8) * OW + y0 + tx];
    __syncthreads();
#pragma unroll
    for (int k = 0; k < 4; k++) {
        size_t oi = (size_t)(y0 + ty + k * 8) * OW + x0 + tx;
        o[oi] += tile[tx][ty + k * 8];
    }
}

extern "C" void kernel_launch(void* const* d_in, const int* in_sizes, int n_in,
                              void* d_out, int out_size) {
    const float* acc = (const float*)d_in[0];
    float* out = (float*)d_out;

    k_trig<<<1, 192>>>();
    k_transpose<<<dim3(AR / 32, NC / 32), dim3(32, 8)>>>(acc);
    k_tab<<<NA * HW / 256, 256>>>();          // 46080 blocks
    k_pass<1><<<2048, 256>>>(out);            // pass B -> g_pBT
    k_pass<0><<<2048, 256>>>(out);            // pass A -> out
    k_merge<<<dim3(8, 8, 256), dim3(32, 8)>>>(out);
}

// round 5
// speedup vs baseline: 1.5817x; 1.1811x over previous
#include <cuda_runtime.h>

// Inverse discrete Hough transform, round 5:
//  - offset tables preloaded to SMEM per CTA (kills table latency on critical path)
//  - 8-px strips split into 2 chains of 4 (heads at p=0, p=4), 2-angle interleave
//    -> 4 independent load chains per warp
// out[nc,y,x] = sum_a accT[a*400+r(a,y,x)][nc]
// Pass A: angles 45..134, strips along x, writes out.
// Pass B: angles 0..44 & 135..179, strips along y, writes pBT[nc][x][y]; merged.

#define NA 180
#define NR 400
#define NC 256
#define OH 256
#define OW 256
#define AR (NA * NR)      // 72000
#define HW (OH * OW)      // 65536
#define NSTRIP 8192       // 65536 px / 8 per strip

typedef unsigned long long ull;

__device__ float  g_accT[AR * NC];                   // 73.7 MB: [a*400+r][nc]
__device__ float2 g_trig[NA];
__device__ unsigned g_offA[(size_t)NSTRIP * 90 * 8]; // [strip][arel][p] byte offsets
__device__ unsigned g_offB[(size_t)NSTRIP * 90 * 8];
__device__ float  g_pBT[NC * HW];                    // pass-B partial, [nc][x][y]

__device__ __forceinline__ ull fadd2(ull a, ull b) {
    ull r;
    asm("add.rn.f32x2 %0, %1, %2;" : "=l"(r) : "l"(a), "l"(b));
    return r;
}
__device__ __forceinline__ float u64lo(ull u) {
    float a, b; asm("mov.b64 {%0,%1}, %2;" : "=f"(a), "=f"(b) : "l"(u)); return a;
}
__device__ __forceinline__ float u64hi(ull u) {
    float a, b; asm("mov.b64 {%0,%1}, %2;" : "=f"(a), "=f"(b) : "l"(u)); return b;
}

// unconditional 16B gather
#define LDG2(v0, v1, addr)                                             \
    asm("ld.global.nc.v2.u64 {%0,%1}, [%2];"                           \
        : "=l"(v0), "=l"(v1) : "l"(addr))
// predicated gather: load only if oc != op (else keep previous registers)
#define PLDG2(v0, v1, oc, op, addr)                                    \
    asm("{\n\t.reg .pred q;\n\tsetp.ne.u32 q, %2, %3;\n\t"             \
        "@q ld.global.nc.v2.u64 {%0,%1}, [%4];\n\t}"                   \
        : "+l"(v0), "+l"(v1) : "r"(oc), "r"(op), "l"(addr))

__global__ void k_trig() {
    int a = threadIdx.x;
    if (a < NA) {
        // f32 theta (rn multiply), then correctly-rounded f32 cos/sin via
        // double (immune to fast-math; matches the JAX reference bit-exactly).
        float t = __fmul_rn((float)a, (float)(3.14159265358979323846 / 180.0));
        double td = (double)t;
        g_trig[a] = make_float2((float)cos(td), (float)sin(td));
    }
}

// 32x32 tiled transpose of acc[256][72000] -> g_accT[72000][256]
__global__ void k_transpose(const float* __restrict__ in) {
    __shared__ float tile[32][33];
    int tx = threadIdx.x, ty = threadIdx.y;           // 32 x 8
    int ar = blockIdx.x * 32 + tx;
#pragma unroll
    for (int k = 0; k < 4; k++)
        tile[ty + k * 8][tx] = in[(size_t)(blockIdx.y * 32 + ty + k * 8) * AR + ar];
    __syncthreads();
    int nc2 = blockIdx.y * 32 + tx;
#pragma unroll
    for (int k = 0; k < 4; k++)
        g_accT[(size_t)(blockIdx.x * 32 + ty + k * 8) * NC + nc2] = tile[tx][ty + k * 8];
}

// Precompute exact rho byte-offset tables: [strip][arel][p].
__global__ void k_tab() {
    int idx = blockIdx.x * 256 + threadIdx.x;   // 180 * 65536 threads
    int p = idx & 7;
    int s = (idx >> 3) & (NSTRIP - 1);
    int a = idx >> 16;
    bool isA = (a >= 45 && a < 135);
    int line = s >> 5, q0 = (s & 31) << 3;
    int x = isA ? (q0 + p) : line;
    int y = isA ? line : (q0 + p);
    float2 cs = g_trig[a];
    // exact reference arithmetic: rn(rn(xc*cos) + rn(yc*sin)), round-half-even
    float sum = __fadd_rn(__fmul_rn((float)(x - OW / 2), cs.x),
                          __fmul_rn((float)(y - OH / 2), cs.y));
    unsigned off = (unsigned)(a * NR + __float2int_rn(sum) + NR / 2) << 10;
    int arel = isA ? (a - 45) : (a < 45 ? a : a - 90);
    unsigned* tab = isA ? g_offA : g_offB;
    tab[((size_t)s * 90 + arel) * 8 + p] = off;
}

// Main pass. PASS=0: x-strips -> outp. PASS=1: y-strips -> g_pBT.
// CTA = 8 warps = 4 strips x 2 channel-halves; offset table in SMEM.
template <int PASS>
__global__ __launch_bounds__(256, 3) void k_pass(float* __restrict__ outp) {
    __shared__ uint4 stab[4 * 90 * 2];   // 4 strips x 90 angles x 8 offsets

    const unsigned* tab = (PASS == 0) ? g_offA : g_offB;
    float* dst = (PASS == 0) ? outp : g_pBT;
    int tid = threadIdx.x;

    // cooperative preload of this CTA's 4 strip tables (11.5 KB)
    {
        const uint4* gsrc =
            (const uint4*)(tab + (size_t)blockIdx.x * 4 * 90 * 8);
#pragma unroll
        for (int i = 0; i < 3; i++) {
            int j = tid + i * 256;
            if (j < 720) stab[j] = __ldg(gsrc + j);
        }
    }
    __syncthreads();

    int w = tid >> 5, l = tid & 31;
    int half = w & 1, sl = w >> 1;            // strip-local 0..3
    int s = blockIdx.x * 4 + sl;
    int line = s >> 5, p0 = (s & 31) << 3;

    ull base;
    {
        const char* gp = (const char*)g_accT + half * 512 + l * 16;
        asm("cvta.to.global.u64 %0, %1;" : "=l"(base) : "l"(gp));
    }

    // acc[2p] = channels (c0,c0+1), acc[2p+1] = (c0+2,c0+3) for pixel p
    ull acc[16];
#pragma unroll
    for (int i = 0; i < 16; i++) acc[i] = 0ull;

    const uint4* tp = &stab[sl * 180];

    for (int it = 0; it < 45; it++) {
        uint4 A0 = tp[0], A1 = tp[1];    // angle ar:   px0-3, px4-7
        uint4 B0 = tp[2], B1 = tp[3];    // angle ar+1
        tp += 4;
        unsigned oa[8] = {A0.x, A0.y, A0.z, A0.w, A1.x, A1.y, A1.z, A1.w};
        unsigned ob[8] = {B0.x, B0.y, B0.z, B0.w, B1.x, B1.y, B1.z, B1.w};

        ull va0, va1, ua0, ua1, vb0, vb1, ub0, ub1;
        // 4 chain heads (independent)
        LDG2(va0, va1, base + oa[0]);
        LDG2(ua0, ua1, base + oa[4]);
        LDG2(vb0, vb1, base + ob[0]);
        LDG2(ub0, ub1, base + ob[4]);
        acc[0] = fadd2(fadd2(acc[0], va0), vb0);
        acc[1] = fadd2(fadd2(acc[1], va1), vb1);
        acc[8] = fadd2(fadd2(acc[8], ua0), ub0);
        acc[9] = fadd2(fadd2(acc[9], ua1), ub1);
#pragma unroll
        for (int p = 1; p < 4; p++) {
            PLDG2(va0, va1, oa[p],     oa[p - 1], base + oa[p]);
            PLDG2(ua0, ua1, oa[4 + p], oa[3 + p], base + oa[4 + p]);
            PLDG2(vb0, vb1, ob[p],     ob[p - 1], base + ob[p]);
            PLDG2(ub0, ub1, ob[4 + p], ob[3 + p], base + ob[4 + p]);
            acc[2 * p]         = fadd2(fadd2(acc[2 * p],         va0), vb0);
            acc[2 * p + 1]     = fadd2(fadd2(acc[2 * p + 1],     va1), vb1);
            acc[2 * p + 8]     = fadd2(fadd2(acc[2 * p + 8],     ua0), ub0);
            acc[2 * p + 9]     = fadd2(fadd2(acc[2 * p + 9],     ua1), ub1);
        }
    }

    // store: lane channels c0..c0+3, 8 strip pixels contiguous in dst
    int chb = half * 128 + l * 4;
    float* op = dst + (size_t)chb * HW + (line << 8) + p0;
#pragma unroll
    for (int j = 0; j < 4; j++) {
        float t[8];
#pragma unroll
        for (int p = 0; p < 8; p++) {
            ull u = acc[2 * p + (j >> 1)];
            t[p] = (j & 1) ? u64hi(u) : u64lo(u);
        }
        float4* q = (float4*)(op + (size_t)j * HW);
        q[0] = make_float4(t[0], t[1], t[2], t[3]);
        q[1] = make_float4(t[4], t[5], t[6], t[7]);
    }
}

// out[nc][y][x] += g_pBT[nc][x][y]
__global__ void k_merge(float* __restrict__ out) {
    __shared__ float tile[32][33];
    int tx = threadIdx.x, ty = threadIdx.y;           // 32 x 8
    const float* src = g_pBT + (size_t)blockIdx.z * HW;
    float* o = out + (size_t)blockIdx.z * HW;
    int x0 = blockIdx.x * 32, y0 = blockIdx.y * 32;
#pragma unroll
    for (int k = 0; k < 4; k++)
        tile[ty + k * 8][tx] = src[(size_t)(x0 + ty + k * 8) * OW + y0 + tx];
    __syncthreads();
#pragma unroll
    for (int k = 0; k < 4; k++) {
        size_t oi = (size_t)(y0 + ty + k * 8) * OW + x0 + tx;
        o[oi] += tile[tx][ty + k * 8];
    }
}

extern "C" void kernel_launch(void* const* d_in, const int* in_sizes, int n_in,
                              void* d_out, int out_size) {
    const float* acc = (const float*)d_in[0];
    float* out = (float*)d_out;

    k_trig<<<1, 192>>>();
    k_transpose<<<dim3(AR / 32, NC / 32), dim3(32, 8)>>>(acc);
    k_tab<<<NA * HW / 256, 256>>>();          // 46080 blocks
    k_pass<1><<<2048, 256>>>(out);            // pass B -> g_pBT
    k_pass<0><<<2048, 256>>>(out);            // pass A -> out
    k_merge<<<dim3(8, 8, 256), dim3(32, 8)>>>(out);
}